// round 13
// baseline (speedup 1.0000x reference)
#include <cuda_runtime.h>
#include <cstdint>

// Problem dims
#define Bb 16384
#define Hh 1024
#define Nn 4096   // 4*H
#define Kk 2048   // D + H

// GEMM tiling: CTA 128x256x32, 8 warps, warp tile 64x64
#define BM 128
#define BN 256
#define BK 32
#define KT (Kk / BK)        // 64
#define STAGES 4
#define A_FLOATS (BM * BK)              // 4096
#define B_FLOATS (BN * BK)              // 8192
#define STAGE_FLOATS (A_FLOATS + B_FLOATS)   // 12288
#define GEMM_SMEM_BYTES (STAGES * STAGE_FLOATS * 4)  // 196608 = 192KB

// Scratch (device globals — allocation-free per harness rules)
__device__ float g_A[(size_t)Bb * Kk];     // [x | h], tf32-rounded, K-major
__device__ float g_W[(size_t)Nn * Kk];     // [Wi | Wh], tf32-rounded, K-major (gate-blocked)
__device__ float g_pre[(size_t)Bb * Nn];   // pre-activations

__device__ __forceinline__ float rna_tf32(float v) {
    uint32_t u; asm("cvt.rna.tf32.f32 %0, %1;" : "=r"(u) : "f"(v));
    return __uint_as_float(u);
}

// ---------------------------------------------------------------------------
// Pack kernels: concatenate along K and round to tf32 once.
// ---------------------------------------------------------------------------
__global__ void pack_A(const float* __restrict__ x, const float* __restrict__ h) {
    size_t i = (size_t)blockIdx.x * blockDim.x + threadIdx.x;
    size_t b = i >> 9;
    int k4 = (int)(i & 511);
    float4 v = (k4 < 256) ? reinterpret_cast<const float4*>(x + b * 1024)[k4]
                          : reinterpret_cast<const float4*>(h + b * 1024)[k4 - 256];
    float4 o;
    o.x = rna_tf32(v.x); o.y = rna_tf32(v.y); o.z = rna_tf32(v.z); o.w = rna_tf32(v.w);
    reinterpret_cast<float4*>(g_A)[i] = o;
}
__global__ void pack_W(const float* __restrict__ Wi, const float* __restrict__ Wh) {
    size_t i = (size_t)blockIdx.x * blockDim.x + threadIdx.x;
    size_t n = i >> 9;
    int k4 = (int)(i & 511);
    float4 v = (k4 < 256) ? reinterpret_cast<const float4*>(Wi + n * 1024)[k4]
                          : reinterpret_cast<const float4*>(Wh + n * 1024)[k4 - 256];
    float4 o;
    o.x = rna_tf32(v.x); o.y = rna_tf32(v.y); o.z = rna_tf32(v.z); o.w = rna_tf32(v.w);
    reinterpret_cast<float4*>(g_W)[i] = o;
}

// ---------------------------------------------------------------------------
// TF32 mma.sync GEMM: g_pre = g_A (16384x2048) * g_W^T (2048x4096)
// ---------------------------------------------------------------------------
__device__ __forceinline__ int swz(int r, int c) {
    // XOR swizzle: conflict-free for the 16B cp.async stores and the
    // m16n8k8 fragment loads.
    return r * BK + (c ^ ((r & 7) << 2));
}
__device__ __forceinline__ void cp16(uint32_t s, const float* g) {
    asm volatile("cp.async.cg.shared.global [%0], [%1], 16;" :: "r"(s), "l"(g));
}
__device__ __forceinline__ void cp_commit() { asm volatile("cp.async.commit_group;"); }
template <int N>
__device__ __forceinline__ void cp_wait() { asm volatile("cp.async.wait_group %0;" :: "n"(N)); }

__global__ void __launch_bounds__(256, 1) gemm_tf32() {
    extern __shared__ float smem[];
    uint32_t smem_u;
    asm("{ .reg .u64 t; cvta.to.shared.u64 t, %1; cvt.u32.u64 %0, t; }"
        : "=r"(smem_u) : "l"(smem));

    // Band schedule: ntile inner -> one wave shares A band + all of W in L2.
    int bid = blockIdx.x;
    int ntile = bid & 15;     // 16 n-tiles of 256
    int mtile = bid >> 4;     // 128 m-tiles of 128

    int tid = threadIdx.x;
    int lane = tid & 31, warp = tid >> 5;
    int wm = warp & 1, wn = warp >> 1;    // 2 x 4 warp grid, warp tile 64x64
    int rq = lane >> 2, cq = lane & 3;
    // Stagger k8 start between SMSP-co-resident warps (w and w+4) so their
    // LDS bursts interleave with each other's HMMA shadows.
    int stag = (warp >> 2) & 1 ? 2 : 0;

    const float* gA = g_A + (size_t)mtile * BM * Kk;
    const float* gB = g_W + (size_t)ntile * BN * Kk;

    float acc[4][8][4];
#pragma unroll
    for (int i = 0; i < 4; i++)
#pragma unroll
        for (int j = 0; j < 8; j++)
#pragma unroll
            for (int l = 0; l < 4; l++) acc[i][j][l] = 0.f;

    // Prefetch pieces: A (4 cp16) and B in two halves (4 cp16 each),
    // issued spread across the k8 loop.
    auto load_A_part = [&](int s, int kt) {
        uint32_t as = smem_u + (uint32_t)(s * STAGE_FLOATS) * 4;
#pragma unroll
        for (int i = 0; i < 4; i++) {
            int ch = i * 256 + tid;
            int row = ch >> 3, c = ch & 7;
            cp16(as + (uint32_t)swz(row, c * 4) * 4,
                 gA + (size_t)row * Kk + kt * BK + c * 4);
        }
    };
    auto load_B_part = [&](int s, int kt, int half) {
        uint32_t bs = smem_u + (uint32_t)(s * STAGE_FLOATS + A_FLOATS) * 4;
#pragma unroll
        for (int i = 0; i < 4; i++) {
            int ch = (half * 4 + i) * 256 + tid;
            int row = ch >> 3, c = ch & 7;
            cp16(bs + (uint32_t)swz(row, c * 4) * 4,
                 gB + (size_t)row * Kk + kt * BK + c * 4);
        }
    };
    auto load_stage = [&](int s, int kt) {
        load_A_part(s, kt); load_B_part(s, kt, 0); load_B_part(s, kt, 1);
    };

#pragma unroll
    for (int s = 0; s < STAGES - 1; s++) { load_stage(s, s); cp_commit(); }

    for (int kt = 0; kt < KT; kt++) {
        cp_wait<STAGES - 2>();
        __syncthreads();

        int pf = kt + STAGES - 1;
        bool do_pf = (pf < KT);
        int ps = pf & (STAGES - 1);

        const float* as = smem + (kt & (STAGES - 1)) * STAGE_FLOATS;
        const float* bs = as + A_FLOATS;

        // Double-buffered fragments, staggered k8 order.
        uint32_t fa[2][4][4], fb[2][8][2];
        auto ldfrag = [&](int bufi, int k8i) {
            int k0 = ((k8i + stag) & 3) * 8 + cq;
#pragma unroll
            for (int mi = 0; mi < 4; mi++) {
                int r = wm * 64 + mi * 16 + rq;
                fa[bufi][mi][0] = __float_as_uint(as[swz(r,     k0)]);
                fa[bufi][mi][1] = __float_as_uint(as[swz(r + 8, k0)]);
                fa[bufi][mi][2] = __float_as_uint(as[swz(r,     k0 + 4)]);
                fa[bufi][mi][3] = __float_as_uint(as[swz(r + 8, k0 + 4)]);
            }
#pragma unroll
            for (int ni = 0; ni < 8; ni++) {
                int rn = wn * 64 + ni * 8 + rq;
                fb[bufi][ni][0] = __float_as_uint(bs[swz(rn, k0)]);
                fb[bufi][ni][1] = __float_as_uint(bs[swz(rn, k0 + 4)]);
            }
        };

        ldfrag(0, 0);
#pragma unroll
        for (int k8i = 0; k8i < 4; k8i++) {
            int cur = k8i & 1;
            if (k8i < 3) ldfrag(cur ^ 1, k8i + 1);
            // Spread next-stage global prefetch across the k8 loop.
            if (do_pf) {
                if (k8i == 0) load_A_part(ps, pf);
                else if (k8i == 1) load_B_part(ps, pf, 0);
                else if (k8i == 2) load_B_part(ps, pf, 1);
            }
#pragma unroll
            for (int mi = 0; mi < 4; mi++)
#pragma unroll
                for (int ni = 0; ni < 8; ni++) {
                    float* c = acc[mi][ni];
                    asm volatile(
                        "mma.sync.aligned.m16n8k8.row.col.f32.tf32.tf32.f32 "
                        "{%0,%1,%2,%3}, {%4,%5,%6,%7}, {%8,%9}, {%0,%1,%2,%3};"
                        : "+f"(c[0]), "+f"(c[1]), "+f"(c[2]), "+f"(c[3])
                        : "r"(fa[cur][mi][0]), "r"(fa[cur][mi][1]),
                          "r"(fa[cur][mi][2]), "r"(fa[cur][mi][3]),
                          "r"(fb[cur][ni][0]), "r"(fb[cur][ni][1]));
                }
        }
        cp_commit();
    }

    // Epilogue: store fp32 pre-activations (coalesced float2)
    size_t baseM = (size_t)mtile * BM + wm * 64;
    size_t baseN = (size_t)ntile * BN + wn * 64;
#pragma unroll
    for (int mi = 0; mi < 4; mi++)
#pragma unroll
        for (int ni = 0; ni < 8; ni++) {
            size_t r = baseM + mi * 16 + rq;
            size_t cc = baseN + ni * 8 + cq * 2;
            *reinterpret_cast<float2*>(g_pre + r * Nn + cc) =
                make_float2(acc[mi][ni][0], acc[mi][ni][1]);
            *reinterpret_cast<float2*>(g_pre + (r + 8) * Nn + cc) =
                make_float2(acc[mi][ni][2], acc[mi][ni][3]);
        }
}

// ---------------------------------------------------------------------------
// Elementwise LSTM gate update (float4) — measured at its DRAM floor (~79us)
// ---------------------------------------------------------------------------
__device__ __forceinline__ float sigm(float x) { return 1.f / (1.f + __expf(-x)); }
__device__ __forceinline__ float tanh_f(float x) { return 2.f * sigm(2.f * x) - 1.f; }

__global__ void lstm_elem(const float* __restrict__ c, const float* __restrict__ bi,
                          float* __restrict__ out, int out_size) {
    int i4 = blockIdx.x * blockDim.x + threadIdx.x;  // float4 index
    int b = i4 >> 8, h4 = i4 & 255;
    const float4* p  = reinterpret_cast<const float4*>(g_pre + (size_t)b * Nn);
    const float4* b4 = reinterpret_cast<const float4*>(bi);

    float4 pi = p[h4],       vb0 = b4[h4];
    float4 pf = p[256 + h4], vb1 = b4[256 + h4];
    float4 pg = p[512 + h4], vb2 = b4[512 + h4];
    float4 po = p[768 + h4], vb3 = b4[768 + h4];
    float4 cv = reinterpret_cast<const float4*>(c)[i4];

    float4 go, nh, nc;
    {
        float gi, gf, gg, gO, t;
#define LANE(W)                                                         \
        gi = sigm(pi.W + vb0.W); gf = sigm(pf.W + vb1.W);               \
        gg = tanh_f(pg.W + vb2.W); gO = sigm(po.W + vb3.W);             \
        nc.W = gf * cv.W + gi * gg; t = tanh_f(nc.W);                   \
        nh.W = gO * t; go.W = gO;
        LANE(x) LANE(y) LANE(z) LANE(w)
#undef LANE
    }

    float4* o4 = reinterpret_cast<float4*>(out);
    o4[i4] = go;
    if (out_size >= 3 * Bb * Hh) {
        o4[(Bb * Hh / 4) + i4]     = nh;
        o4[(2 * Bb * Hh / 4) + i4] = nc;
    }
}

// ---------------------------------------------------------------------------
// Launch: pack -> GEMM -> elementwise (graph-capturable)
// ---------------------------------------------------------------------------
extern "C" void kernel_launch(void* const* d_in, const int* in_sizes, int n_in,
                              void* d_out, int out_size) {
    const float* x  = (const float*)d_in[0];
    const float* h  = (const float*)d_in[1];
    const float* c  = (const float*)d_in[2];
    const float* Wi = (const float*)d_in[3];
    const float* bi = (const float*)d_in[4];
    const float* Wh = (const float*)d_in[5];
    float* out = (float*)d_out;

    pack_A<<<32768, 256>>>(x, h);
    pack_W<<<8192, 256>>>(Wi, Wh);

    cudaFuncSetAttribute(gemm_tf32, cudaFuncAttributeMaxDynamicSharedMemorySize,
                         GEMM_SMEM_BYTES);
    gemm_tf32<<<(Bb / BM) * (Nn / BN), 256, GEMM_SMEM_BYTES>>>();  // 2048 CTAs

    lstm_elem<<<(Bb * Hh / 4) / 256, 256>>>(c, bi, out, out_size);
}

// round 16
// speedup vs baseline: 2.4059x; 2.4059x over previous
#include <cuda_runtime.h>
#include <cuda_fp16.h>
#include <cstdint>

// Problem dims
#define Bb 16384
#define Hh 1024
#define Nn 4096   // 4*H
#define Kk 2048   // D + H

// GEMM tiling: CTA 128x256x32(halves), 8 warps, warp tile 64x64
#define BM 128
#define BN 256
#define BK 32               // halves per k-stage (64B rows)
#define KT (Kk / BK)        // 64
#define STAGES 4
#define A_BYTES (BM * BK * 2)            // 8192
#define B_BYTES (BN * BK * 2)            // 16384
#define STAGE_BYTES (A_BYTES + B_BYTES)  // 24576
#define A_WORDS (A_BYTES / 4)            // 2048
#define GEMM_SMEM_BYTES (STAGES * STAGE_BYTES)   // 98304 = 96KB

// Scratch (device globals — allocation-free per harness rules)
__device__ __half g_Ah[(size_t)Bb * Kk];   // [x | h], fp16, K-major (64MB)
__device__ __half g_Wh[(size_t)Nn * Kk];   // [Wi | Wh], fp16, K-major (16MB)
__device__ float  g_pre[(size_t)Bb * Nn];  // pre-activations (256MB)

// ---------------------------------------------------------------------------
// Pack kernels: concatenate along K and convert fp32 -> fp16 (RN).
// Each thread: 8 floats (2 float4 reads) -> 8 halves (1 uint4 write).
// ---------------------------------------------------------------------------
__device__ __forceinline__ uint32_t f16x2(float lo, float hi) {
    uint32_t u;
    asm("cvt.rn.f16x2.f32 %0, %1, %2;" : "=r"(u) : "f"(hi), "f"(lo));
    return u;
}
__device__ __forceinline__ uint4 pack8(float4 v0, float4 v1) {
    uint4 o;
    o.x = f16x2(v0.x, v0.y);
    o.y = f16x2(v0.z, v0.w);
    o.z = f16x2(v1.x, v1.y);
    o.w = f16x2(v1.z, v1.w);
    return o;
}

__global__ void pack_A(const float* __restrict__ x, const float* __restrict__ h) {
    size_t i = (size_t)blockIdx.x * blockDim.x + threadIdx.x;  // 8-float group
    size_t b = i >> 8;                 // 256 groups per row of 2048
    int g8 = (int)(i & 255);
    const float4* src = (g8 < 128)
        ? reinterpret_cast<const float4*>(x + b * 1024) + g8 * 2
        : reinterpret_cast<const float4*>(h + b * 1024) + (g8 - 128) * 2;
    reinterpret_cast<uint4*>(g_Ah)[i] = pack8(src[0], src[1]);
}
__global__ void pack_W(const float* __restrict__ Wi, const float* __restrict__ Wh) {
    size_t i = (size_t)blockIdx.x * blockDim.x + threadIdx.x;
    size_t n = i >> 8;
    int g8 = (int)(i & 255);
    const float4* src = (g8 < 128)
        ? reinterpret_cast<const float4*>(Wi + n * 1024) + g8 * 2
        : reinterpret_cast<const float4*>(Wh + n * 1024) + (g8 - 128) * 2;
    reinterpret_cast<uint4*>(g_Wh)[i] = pack8(src[0], src[1]);
}

// ---------------------------------------------------------------------------
// FP16 mma.sync GEMM (m16n8k16): g_pre = g_Ah (16384x2048) * g_Wh^T
// ---------------------------------------------------------------------------
// 16B-chunk XOR swizzle: row r (64B = 4 chunks), chunk c -> c ^ ((r>>1)&3).
// Fragment loads (u32 granularity): word w (0..15 per row) ->
//   r*16 + (((w>>2) ^ ((r>>1)&3)) << 2) + (w&3)
// Verified: for each frag pattern (8 rows x 4 cq), all 32 lanes hit distinct banks.
__device__ __forceinline__ int swzw(int r, int w) {
    return r * 16 + ((((w >> 2) ^ ((r >> 1) & 3))) << 2) + (w & 3);
}
__device__ __forceinline__ void cp16(uint32_t s, const void* g) {
    asm volatile("cp.async.cg.shared.global [%0], [%1], 16;" :: "r"(s), "l"(g));
}
__device__ __forceinline__ void cp_commit() { asm volatile("cp.async.commit_group;"); }
template <int N>
__device__ __forceinline__ void cp_wait() { asm volatile("cp.async.wait_group %0;" :: "n"(N)); }

__global__ void __launch_bounds__(256, 1) gemm_f16() {
    extern __shared__ char smem[];
    uint32_t smem_u;
    asm("{ .reg .u64 t; cvta.to.shared.u64 t, %1; cvt.u32.u64 %0, t; }"
        : "=r"(smem_u) : "l"(smem));

    // Band schedule: ntile inner -> one wave shares A band + all of W in L2.
    int bid = blockIdx.x;
    int ntile = bid & 15;     // 16 n-tiles of 256
    int mtile = bid >> 4;     // 128 m-tiles of 128

    int tid = threadIdx.x;
    int lane = tid & 31, warp = tid >> 5;
    int wm = warp & 1, wn = warp >> 1;    // 2 x 4 warp grid, warp tile 64x64
    int rq = lane >> 2, cq = lane & 3;

    const __half* gA = g_Ah + (size_t)mtile * BM * Kk;
    const __half* gB = g_Wh + (size_t)ntile * BN * Kk;

    float acc[4][8][4];
#pragma unroll
    for (int i = 0; i < 4; i++)
#pragma unroll
        for (int j = 0; j < 8; j++)
#pragma unroll
            for (int l = 0; l < 4; l++) acc[i][j][l] = 0.f;

    auto load_stage = [&](int s, int kt) {
        uint32_t as = smem_u + (uint32_t)(s * STAGE_BYTES);
        uint32_t bs = as + A_BYTES;
        // A: 512 16B chunks (128 rows x 4)
#pragma unroll
        for (int i = 0; i < 2; i++) {
            int ch = i * 256 + tid;
            int row = ch >> 2, c = ch & 3;
            uint32_t cs = (uint32_t)(c ^ ((row >> 1) & 3));
            cp16(as + (uint32_t)row * 64 + cs * 16,
                 gA + (size_t)row * Kk + kt * BK + c * 8);
        }
        // B: 1024 16B chunks (256 rows x 4)
#pragma unroll
        for (int i = 0; i < 4; i++) {
            int ch = i * 256 + tid;
            int row = ch >> 2, c = ch & 3;
            uint32_t cs = (uint32_t)(c ^ ((row >> 1) & 3));
            cp16(bs + (uint32_t)row * 64 + cs * 16,
                 gB + (size_t)row * Kk + kt * BK + c * 8);
        }
    };

#pragma unroll
    for (int s = 0; s < STAGES - 1; s++) { load_stage(s, s); cp_commit(); }

    for (int kt = 0; kt < KT; kt++) {
        cp_wait<STAGES - 2>();
        __syncthreads();

        int pf = kt + STAGES - 1;
        if (pf < KT) load_stage(pf & (STAGES - 1), pf);
        cp_commit();

        const uint32_t* as =
            reinterpret_cast<const uint32_t*>(smem + (kt & (STAGES - 1)) * STAGE_BYTES);
        const uint32_t* bs = as + A_WORDS;

#pragma unroll
        for (int k16 = 0; k16 < 2; k16++) {
            int w0 = k16 * 8 + cq;
            int w1 = w0 + 4;
            uint32_t a[4][4], b[8][2];
#pragma unroll
            for (int mi = 0; mi < 4; mi++) {
                int r = wm * 64 + mi * 16 + rq;
                a[mi][0] = as[swzw(r,     w0)];
                a[mi][1] = as[swzw(r + 8, w0)];
                a[mi][2] = as[swzw(r,     w1)];
                a[mi][3] = as[swzw(r + 8, w1)];
            }
#pragma unroll
            for (int ni = 0; ni < 8; ni++) {
                int rn = wn * 64 + ni * 8 + rq;
                b[ni][0] = bs[swzw(rn, w0)];
                b[ni][1] = bs[swzw(rn, w1)];
            }
#pragma unroll
            for (int mi = 0; mi < 4; mi++)
#pragma unroll
                for (int ni = 0; ni < 8; ni++) {
                    float* c = acc[mi][ni];
                    asm volatile(
                        "mma.sync.aligned.m16n8k16.row.col.f32.f16.f16.f32 "
                        "{%0,%1,%2,%3}, {%4,%5,%6,%7}, {%8,%9}, {%0,%1,%2,%3};"
                        : "+f"(c[0]), "+f"(c[1]), "+f"(c[2]), "+f"(c[3])
                        : "r"(a[mi][0]), "r"(a[mi][1]), "r"(a[mi][2]), "r"(a[mi][3]),
                          "r"(b[ni][0]), "r"(b[ni][1]));
                }
        }
    }

    // Epilogue: store fp32 pre-activations (coalesced float2)
    size_t baseM = (size_t)mtile * BM + wm * 64;
    size_t baseN = (size_t)ntile * BN + wn * 64;
#pragma unroll
    for (int mi = 0; mi < 4; mi++)
#pragma unroll
        for (int ni = 0; ni < 8; ni++) {
            size_t r = baseM + mi * 16 + rq;
            size_t cc = baseN + ni * 8 + cq * 2;
            *reinterpret_cast<float2*>(g_pre + r * Nn + cc) =
                make_float2(acc[mi][ni][0], acc[mi][ni][1]);
            *reinterpret_cast<float2*>(g_pre + (r + 8) * Nn + cc) =
                make_float2(acc[mi][ni][2], acc[mi][ni][3]);
        }
}

// ---------------------------------------------------------------------------
// Elementwise LSTM gate update (float4) — at its DRAM floor (~79us)
// ---------------------------------------------------------------------------
__device__ __forceinline__ float sigm(float x) { return 1.f / (1.f + __expf(-x)); }
__device__ __forceinline__ float tanh_f(float x) { return 2.f * sigm(2.f * x) - 1.f; }

__global__ void lstm_elem(const float* __restrict__ c, const float* __restrict__ bi,
                          float* __restrict__ out, int out_size) {
    int i4 = blockIdx.x * blockDim.x + threadIdx.x;  // float4 index
    int b = i4 >> 8, h4 = i4 & 255;
    const float4* p  = reinterpret_cast<const float4*>(g_pre + (size_t)b * Nn);
    const float4* b4 = reinterpret_cast<const float4*>(bi);

    float4 pi = p[h4],       vb0 = b4[h4];
    float4 pf = p[256 + h4], vb1 = b4[256 + h4];
    float4 pg = p[512 + h4], vb2 = b4[512 + h4];
    float4 po = p[768 + h4], vb3 = b4[768 + h4];
    float4 cv = reinterpret_cast<const float4*>(c)[i4];

    float4 go, nh, nc;
    {
        float gi, gf, gg, gO, t;
#define LANE(W)                                                         \
        gi = sigm(pi.W + vb0.W); gf = sigm(pf.W + vb1.W);               \
        gg = tanh_f(pg.W + vb2.W); gO = sigm(po.W + vb3.W);             \
        nc.W = gf * cv.W + gi * gg; t = tanh_f(nc.W);                   \
        nh.W = gO * t; go.W = gO;
        LANE(x) LANE(y) LANE(z) LANE(w)
#undef LANE
    }

    float4* o4 = reinterpret_cast<float4*>(out);
    o4[i4] = go;
    if (out_size >= 3 * Bb * Hh) {
        o4[(Bb * Hh / 4) + i4]     = nh;
        o4[(2 * Bb * Hh / 4) + i4] = nc;
    }
}

// ---------------------------------------------------------------------------
// Launch: pack -> GEMM -> elementwise (graph-capturable)
// ---------------------------------------------------------------------------
extern "C" void kernel_launch(void* const* d_in, const int* in_sizes, int n_in,
                              void* d_out, int out_size) {
    const float* x  = (const float*)d_in[0];
    const float* h  = (const float*)d_in[1];
    const float* c  = (const float*)d_in[2];
    const float* Wi = (const float*)d_in[3];
    const float* bi = (const float*)d_in[4];
    const float* Wh = (const float*)d_in[5];
    float* out = (float*)d_out;

    pack_A<<<16384, 256>>>(x, h);     // B*K/8 groups
    pack_W<<<4096, 256>>>(Wi, Wh);    // N*K/8 groups

    cudaFuncSetAttribute(gemm_f16, cudaFuncAttributeMaxDynamicSharedMemorySize,
                         GEMM_SMEM_BYTES);
    gemm_f16<<<(Bb / BM) * (Nn / BN), 256, GEMM_SMEM_BYTES>>>();  // 2048 CTAs

    lstm_elem<<<(Bb * Hh / 4) / 256, 256>>>(c, bi, out, out_size);
}